// round 12
// baseline (speedup 1.0000x reference)
#include <cuda_runtime.h>
#include <math.h>

// ---------------------------------------------------------------------------
// PhysicsEmbedding: algebraic collapse of the whole pipeline.
//   B=32, S=4096, D=1024, H=256
// out[b,s,:] = A1·p[b,s] + A2·vel[b,s] + A3·acc[b,s] + g[b,:]
// g[b,:] = A4 @ freq[b] + c,  freq = |16-bin DFT| per channel
// ---------------------------------------------------------------------------

#define B_ 32
#define S_ 4096
#define D_ 1024
#define H_ 256
#define SCHUNK 16
#define NDFT 64                     // b*2 + chunk   (2 S-chunks of 2048)
#define NCOEFF 64                   // 16 d-rows per block
#define NPART 4                     // DFT partials per bin: chunk*2 + half

__device__ float2 g_dpart[B_ * 32 * NPART];    // DFT partials [b][j][q]
__device__ float g_a1x[D_], g_a1y[D_];
__device__ float g_a2x[D_], g_a2y[D_];
__device__ float g_a3x[D_], g_a3y[D_];
__device__ float g_A4T[32 * D_];               // transposed: [j][d]
__device__ float g_cbias[D_];
__device__ float g_g[B_ * D_];                 // per-batch constant vector

// ---------------------------------------------------------------------------
// 1) Fused precompute, one wave (128 blocks), burst-stage-then-compute.
//    blocks [0,64):  DFT — stage 16KB pattern chunk to smem, then recurrence.
//    blocks [64,128): coeff — stage 16 Wo rows (64KB) to smem, fold from smem.
// ---------------------------------------------------------------------------
__global__ void __launch_bounds__(1024) pre_kernel(
        const float* __restrict__ pattern,
        const float* __restrict__ Wp, const float* __restrict__ bp,
        const float* __restrict__ Wv, const float* __restrict__ bv,
        const float* __restrict__ Wa, const float* __restrict__ ba,
        const float* __restrict__ Wf, const float* __restrict__ bfr,
        const float* __restrict__ Wo, const float* __restrict__ bo) {
    extern __shared__ float smem[];            // 64KB dynamic
    int bx = blockIdx.x;
    int tid = threadIdx.x;
    int lane = tid & 31;
    int w = tid >> 5;

    if (bx < NDFT) {
        // ---- DFT: stage pattern[b, chunk*2048 .. +2048, :] (16KB) ----
        int b = bx >> 1;
        int chunk = bx & 1;
        const float4* src = (const float4*)(pattern + ((size_t)b * S_ + chunk * 2048) * 2);
        ((float4*)smem)[tid] = src[tid];       // 1024 float4, coalesced
        __syncthreads();

        // warp w: bin k = w&15, half = w>>4; 32 samples/lane, BOTH channels
        int k = w & 15;
        int half = w >> 4;
        int tl0 = half * 1024 + lane;          // local t within chunk
        int tg0 = chunk * 2048 + tl0;          // global t
        float a0 = (float)((k * tg0) & (S_ - 1)) * (-1.0f / 2048.0f);
        float as = (float)((k * 32) & (S_ - 1)) * (-1.0f / 2048.0f);
        float wr, wi, sr, si;
        sincospif(a0, &wi, &wr);
        sincospif(as, &si, &sr);

        const float2* sp2 = (const float2*)smem;
        float re0 = 0.f, im0 = 0.f, re1 = 0.f, im1 = 0.f;
#pragma unroll
        for (int i = 0; i < 32; i++) {
            float2 x = sp2[tl0 + i * 32];
            re0 += x.x * wr;  im0 += x.x * wi;
            re1 += x.y * wr;  im1 += x.y * wi;
            float nr = wr * sr - wi * si;      // w *= step
            float ni = wr * si + wi * sr;
            wr = nr; wi = ni;
        }
#pragma unroll
        for (int off = 16; off > 0; off >>= 1) {
            re0 += __shfl_down_sync(0xffffffffu, re0, off);
            im0 += __shfl_down_sync(0xffffffffu, im0, off);
            re1 += __shfl_down_sync(0xffffffffu, re1, off);
            im1 += __shfl_down_sync(0xffffffffu, im1, off);
        }
        if (lane == 0) {
            int q = chunk * 2 + half;
            g_dpart[(b * 32 + k) * NPART + q]      = make_float2(re0, im0);  // ch0
            g_dpart[(b * 32 + 16 + k) * NPART + q] = make_float2(re1, im1);  // ch1
        }
    } else {
        // ---- Coeff: stage 16 Wo rows (64KB) with 4 wide LDGs/thread ----
        int cb = bx - NDFT;
        int d0 = cb * 16;
        const float4* wsrc = (const float4*)(Wo + (size_t)d0 * D_);
        float4 v0 = wsrc[tid];
        float4 v1 = wsrc[tid + 1024];
        float4 v2 = wsrc[tid + 2048];
        float4 v3 = wsrc[tid + 3072];
        float4* sw4 = (float4*)smem;
        sw4[tid] = v0; sw4[tid + 1024] = v1; sw4[tid + 2048] = v2; sw4[tid + 3072] = v3;
        __syncthreads();

        int sub = tid >> 6;                    // row 0..15
        int d = d0 + sub;
        const float* swo = smem + sub * 1024;
        int halfwarp = (tid >> 5) & 1;

        if (halfwarp == 0) {
            // A4T[lane][d] = sum_h swo[768+h] * Wf[h][lane]
            float a0c = 0.f, a1c = 0.f, a2c = 0.f, a3c = 0.f;
#pragma unroll 8
            for (int h = 0; h < H_; h += 4) {
                float4 wv = *(const float4*)(swo + 768 + h);   // LDS.128 bcast
                a0c += wv.x * Wf[(h + 0) * 32 + lane];
                a1c += wv.y * Wf[(h + 1) * 32 + lane];
                a2c += wv.z * Wf[(h + 2) * 32 + lane];
                a3c += wv.w * Wf[(h + 3) * 32 + lane];
            }
            g_A4T[lane * D_ + d] = (a0c + a1c) + (a2c + a3c);
        } else {
            float a1x = 0, a1y = 0, a2x = 0, a2y = 0, a3x = 0, a3y = 0, bias = 0;
#pragma unroll
            for (int h = lane; h < H_; h += 32) {
                float w0 = swo[h];
                float w1 = swo[256 + h];
                float w2 = swo[512 + h];
                float w3 = swo[768 + h];
                a1x += w0 * Wp[h * 2 + 0];  a1y += w0 * Wp[h * 2 + 1];
                a2x += w1 * Wv[h * 2 + 0];  a2y += w1 * Wv[h * 2 + 1];
                a3x += w2 * Wa[h * 2 + 0];  a3y += w2 * Wa[h * 2 + 1];
                bias += w0 * bp[h] + w1 * bv[h] + w2 * ba[h] + w3 * bfr[h];
            }
#pragma unroll
            for (int off = 16; off > 0; off >>= 1) {
                a1x += __shfl_down_sync(0xffffffffu, a1x, off);
                a1y += __shfl_down_sync(0xffffffffu, a1y, off);
                a2x += __shfl_down_sync(0xffffffffu, a2x, off);
                a2y += __shfl_down_sync(0xffffffffu, a2y, off);
                a3x += __shfl_down_sync(0xffffffffu, a3x, off);
                a3y += __shfl_down_sync(0xffffffffu, a3y, off);
                bias += __shfl_down_sync(0xffffffffu, bias, off);
            }
            if (lane == 0) {
                g_a1x[d] = a1x; g_a1y[d] = a1y;
                g_a2x[d] = a2x; g_a2y[d] = a2y;
                g_a3x[d] = a3x; g_a3y[d] = a3y;
                g_cbias[d] = bias + bo[d];
            }
        }
    }
}

// ---------------------------------------------------------------------------
// 2) g[b,d] = cbias[d] + sum_j freq[b,j] * A4T[j][d].
//    grid (B_, 4) x 256 thr; thread = d within 256-chunk (coalesced A4T).
// ---------------------------------------------------------------------------
__global__ void __launch_bounds__(256) gtab_kernel() {
    int b = blockIdx.x;
    int d0 = blockIdx.y * 256;
    int tid = threadIdx.x;
    __shared__ float fr[32];
    if (tid < 32) {
        float re = 0.f, im = 0.f;
#pragma unroll
        for (int q = 0; q < NPART; q++) {
            float2 p = g_dpart[(b * 32 + tid) * NPART + q];
            re += p.x; im += p.y;
        }
        fr[tid] = sqrtf(re * re + im * im);
    }
    __syncthreads();

    int d = d0 + tid;
    float acc = g_cbias[d];
#pragma unroll
    for (int j = 0; j < 32; j++)
        acc += fr[j] * g_A4T[j * D_ + d];           // coalesced, fr broadcast
    g_g[b * D_ + d] = acc;
}

// ---------------------------------------------------------------------------
// 3) Main write kernel: HBM-write bound (537 MB of output), at the roofline.
//    PDL: stage pattern tile first, grid-dependency-sync, then coefficients.
// ---------------------------------------------------------------------------
__global__ void __launch_bounds__(256) main_kernel(const float* __restrict__ pattern,
                                                   float* __restrict__ out) {
    int b = blockIdx.y;
    int s0 = blockIdx.x * SCHUNK;
    int tid = threadIdx.x;
    int d = tid * 4;

    __shared__ float sp[(SCHUNK + 2) * 2];   // pattern[b, s0-2 .. s0+SCHUNK-1]
    if (tid < (SCHUNK + 2) * 2) {
        int s = s0 - 2 + (tid >> 1);
        int c = tid & 1;
        sp[tid] = (s >= 0) ? pattern[((size_t)b * S_ + s) * 2 + c] : 0.0f;
    }
#if __CUDA_ARCH__ >= 900
    cudaGridDependencySynchronize();
#endif
    float4 k1x = *(const float4*)(g_a1x + d);
    float4 k1y = *(const float4*)(g_a1y + d);
    float4 k2x = *(const float4*)(g_a2x + d);
    float4 k2y = *(const float4*)(g_a2y + d);
    float4 k3x = *(const float4*)(g_a3x + d);
    float4 k3y = *(const float4*)(g_a3y + d);
    float4 gg  = *(const float4*)(g_g + b * D_ + d);
    __syncthreads();

    float* op = out + ((size_t)b * S_ + s0) * D_ + d;

#pragma unroll
    for (int i = 0; i < SCHUNK; i++) {
        int s = s0 + i;
        float px = sp[(i + 2) * 2 + 0], py = sp[(i + 2) * 2 + 1];
        float mx = sp[(i + 1) * 2 + 0], my = sp[(i + 1) * 2 + 1];
        float nx = sp[(i + 0) * 2 + 0], ny = sp[(i + 0) * 2 + 1];

        float vx, vy, ax_, ay_;
        if (s == 0) {
            vx = 0.f; vy = 0.f; ax_ = 0.f; ay_ = 0.f;
        } else if (s == 1) {
            vx = px - mx; vy = py - my; ax_ = vx; ay_ = vy;
        } else {
            vx = px - mx; vy = py - my;
            ax_ = px - 2.f * mx + nx; ay_ = py - 2.f * my + ny;
        }

        float4 o;
        o.x = gg.x + k1x.x * px + k1y.x * py + k2x.x * vx + k2y.x * vy + k3x.x * ax_ + k3y.x * ay_;
        o.y = gg.y + k1x.y * px + k1y.y * py + k2x.y * vx + k2y.y * vy + k3x.y * ax_ + k3y.y * ay_;
        o.z = gg.z + k1x.z * px + k1y.z * py + k2x.z * vx + k2y.z * vy + k3x.z * ax_ + k3y.z * ay_;
        o.w = gg.w + k1x.w * px + k1y.w * py + k2x.w * vx + k2y.w * vy + k3x.w * ax_ + k3y.w * ay_;

        *(float4*)(op + (size_t)i * D_) = o;
    }
}

// ---------------------------------------------------------------------------
extern "C" void kernel_launch(void* const* d_in, const int* in_sizes, int n_in,
                              void* d_out, int out_size) {
    const float* pattern = (const float*)d_in[0];
    const float* Wp  = (const float*)d_in[1];
    const float* bp  = (const float*)d_in[2];
    const float* Wv  = (const float*)d_in[3];
    const float* bv  = (const float*)d_in[4];
    const float* Wa  = (const float*)d_in[5];
    const float* ba  = (const float*)d_in[6];
    const float* Wf  = (const float*)d_in[7];
    const float* bfr = (const float*)d_in[8];
    const float* Wo  = (const float*)d_in[9];
    const float* bo  = (const float*)d_in[10];
    float* out = (float*)d_out;

    // 64KB dynamic smem for the staging buffers (host-side attr, no alloc)
    static int smem_set = 0;
    if (!smem_set) {
        cudaFuncSetAttribute(pre_kernel,
                             cudaFuncAttributeMaxDynamicSharedMemorySize, 65536);
        smem_set = 1;
    }

    pre_kernel<<<NDFT + NCOEFF, 1024, 65536>>>(pattern, Wp, bp, Wv, bv, Wa, ba,
                                               Wf, bfr, Wo, bo);
    gtab_kernel<<<dim3(B_, 4), 256>>>();

    // PDL on the final (dominant) kernel: overlap its launch/prologue with
    // gtab; main_kernel pre-syncs before touching precomputed tables.
    cudaLaunchAttribute at[1];
    at[0].id = cudaLaunchAttributeProgrammaticStreamSerialization;
    at[0].val.programmaticStreamSerializationAllowed = 1;

    cudaLaunchConfig_t cfg = {};
    cfg.gridDim = dim3(S_ / SCHUNK, B_);
    cfg.blockDim = dim3(256);
    cfg.stream = 0;
    cfg.attrs = at;
    cfg.numAttrs = 1;
    if (cudaLaunchKernelEx(&cfg, main_kernel, pattern, out) != cudaSuccess) {
        main_kernel<<<dim3(S_ / SCHUNK, B_), 256>>>(pattern, out);
    }
}

// round 13
// speedup vs baseline: 1.2876x; 1.2876x over previous
#include <cuda_runtime.h>
#include <math.h>

// ---------------------------------------------------------------------------
// PhysicsEmbedding: algebraic collapse of the whole pipeline.
//   B=32, S=4096, D=1024, H=256
// out[b,s,:] = A1·p[b,s] + A2·vel[b,s] + A3·acc[b,s] + g[b,:]
// g[b,:] = A4 @ freq[b] + c,  freq = |16-bin DFT| per channel
// ---------------------------------------------------------------------------

#define B_ 32
#define S_ 4096
#define D_ 1024
#define H_ 256
#define SCHUNK 16
#define NDFT 64                     // b*2 + chunk  (2 S-chunks of 2048)
#define NCOEFF 64                   // 16 d-rows per block
#define NPART 4                     // DFT partials per bin: chunk*2 + half

__device__ float2 g_dpart[B_ * 32 * NPART];    // DFT partials [b][j][q]
__device__ float g_a1x[D_], g_a1y[D_];
__device__ float g_a2x[D_], g_a2y[D_];
__device__ float g_a3x[D_], g_a3y[D_];
__device__ float g_A4T[32 * D_];               // transposed: [j][d]
__device__ float g_cbias[D_];
__device__ float g_g[B_ * D_];                 // per-batch constant vector

// ---------------------------------------------------------------------------
// 1) Fused precompute, one wave (128 blocks):
//    blocks [0,64):  DFT partials — float2 loads (both channels per LDG,
//                    full line utilization), 8-wide batches for MLP.
//    blocks [64,128): coefficient folding (R11 structure, direct loads).
// ---------------------------------------------------------------------------
__global__ void __launch_bounds__(1024) pre_kernel(
        const float* __restrict__ pattern,
        const float* __restrict__ Wp, const float* __restrict__ bp,
        const float* __restrict__ Wv, const float* __restrict__ bv,
        const float* __restrict__ Wa, const float* __restrict__ ba,
        const float* __restrict__ Wf, const float* __restrict__ bfr,
        const float* __restrict__ Wo, const float* __restrict__ bo) {
    int bx = blockIdx.x;
    int tid = threadIdx.x;
    int lane = tid & 31;
    int w = tid >> 5;

    if (bx < NDFT) {
        // ---- DFT: warp w handles bin k=w&15, half=w>>4, BOTH channels ----
        int b = bx >> 1;
        int chunk = bx & 1;
        int k = w & 15;
        int half = w >> 4;
        int tl0 = half * 1024 + lane;          // local t within 2048-chunk
        int tg0 = chunk * 2048 + tl0;          // global t
        float a0 = (float)((k * tg0) & (S_ - 1)) * (-1.0f / 2048.0f);
        float as = (float)((k * 32) & (S_ - 1)) * (-1.0f / 2048.0f);
        float wr, wi, sr, si;
        sincospif(a0, &wi, &wr);
        sincospif(as, &si, &sr);

        const float2* pp2 = (const float2*)pattern + (size_t)b * S_ + chunk * 2048;
        float re0 = 0.f, im0 = 0.f, re1 = 0.f, im1 = 0.f;
#pragma unroll
        for (int batch = 0; batch < 4; batch++) {
            float2 x[8];
#pragma unroll
            for (int u = 0; u < 8; u++)        // 8 independent float2 LDGs
                x[u] = pp2[tl0 + (batch * 8 + u) * 32];
#pragma unroll
            for (int u = 0; u < 8; u++) {
                re0 += x[u].x * wr;  im0 += x[u].x * wi;
                re1 += x[u].y * wr;  im1 += x[u].y * wi;
                float nr = wr * sr - wi * si;  // w *= step
                float ni = wr * si + wi * sr;
                wr = nr; wi = ni;
            }
        }
#pragma unroll
        for (int off = 16; off > 0; off >>= 1) {
            re0 += __shfl_down_sync(0xffffffffu, re0, off);
            im0 += __shfl_down_sync(0xffffffffu, im0, off);
            re1 += __shfl_down_sync(0xffffffffu, re1, off);
            im1 += __shfl_down_sync(0xffffffffu, im1, off);
        }
        if (lane == 0) {
            int q = chunk * 2 + half;
            g_dpart[(b * 32 + k) * NPART + q]      = make_float2(re0, im0); // ch0
            g_dpart[(b * 32 + 16 + k) * NPART + q] = make_float2(re1, im1); // ch1
        }
    } else {
        // ---- Coefficient folding: 16 d-rows per block, 64 thr per row ----
        int sub = tid >> 6;                          // 0..15
        int d = (bx - NDFT) * 16 + sub;
        int halfwarp = (tid >> 5) & 1;               // role: 0=A4, 1=small
        const float* wo = Wo + (size_t)d * D_;

        if (halfwarp == 0) {
            float acc[8];
#pragma unroll
            for (int u = 0; u < 8; u++) acc[u] = 0.f;
#pragma unroll 4
            for (int h = 0; h < H_; h += 8) {
#pragma unroll
                for (int u = 0; u < 8; u++)
                    acc[u] += wo[768 + h + u] * Wf[(h + u) * 32 + lane];
            }
            float a4 = ((acc[0] + acc[1]) + (acc[2] + acc[3]))
                     + ((acc[4] + acc[5]) + (acc[6] + acc[7]));
            g_A4T[lane * D_ + d] = a4;               // transposed store
        } else {
            float a1x = 0, a1y = 0, a2x = 0, a2y = 0, a3x = 0, a3y = 0, bias = 0;
#pragma unroll
            for (int h = lane; h < H_; h += 32) {
                float w0 = wo[h];
                float w1 = wo[256 + h];
                float w2 = wo[512 + h];
                float w3 = wo[768 + h];
                a1x += w0 * Wp[h * 2 + 0];  a1y += w0 * Wp[h * 2 + 1];
                a2x += w1 * Wv[h * 2 + 0];  a2y += w1 * Wv[h * 2 + 1];
                a3x += w2 * Wa[h * 2 + 0];  a3y += w2 * Wa[h * 2 + 1];
                bias += w0 * bp[h] + w1 * bv[h] + w2 * ba[h] + w3 * bfr[h];
            }
#pragma unroll
            for (int off = 16; off > 0; off >>= 1) {
                a1x += __shfl_down_sync(0xffffffffu, a1x, off);
                a1y += __shfl_down_sync(0xffffffffu, a1y, off);
                a2x += __shfl_down_sync(0xffffffffu, a2x, off);
                a2y += __shfl_down_sync(0xffffffffu, a2y, off);
                a3x += __shfl_down_sync(0xffffffffu, a3x, off);
                a3y += __shfl_down_sync(0xffffffffu, a3y, off);
                bias += __shfl_down_sync(0xffffffffu, bias, off);
            }
            if (lane == 0) {
                g_a1x[d] = a1x; g_a1y[d] = a1y;
                g_a2x[d] = a2x; g_a2y[d] = a2y;
                g_a3x[d] = a3x; g_a3y[d] = a3y;
                g_cbias[d] = bias + bo[d];
            }
        }
    }
}

// ---------------------------------------------------------------------------
// 2) g[b,d] = cbias[d] + sum_j freq[b,j] * A4T[j][d].
//    grid (B_, 4) x 256 thr; thread = d within 256-chunk (coalesced A4T).
// ---------------------------------------------------------------------------
__global__ void __launch_bounds__(256) gtab_kernel() {
    int b = blockIdx.x;
    int d0 = blockIdx.y * 256;
    int tid = threadIdx.x;
    __shared__ float fr[32];
    if (tid < 32) {
        float re = 0.f, im = 0.f;
#pragma unroll
        for (int q = 0; q < NPART; q++) {
            float2 p = g_dpart[(b * 32 + tid) * NPART + q];
            re += p.x; im += p.y;
        }
        fr[tid] = sqrtf(re * re + im * im);
    }
    __syncthreads();

    int d = d0 + tid;
    float acc = g_cbias[d];
#pragma unroll
    for (int j = 0; j < 32; j++)
        acc += fr[j] * g_A4T[j * D_ + d];           // coalesced, fr broadcast
    g_g[b * D_ + d] = acc;
}

// ---------------------------------------------------------------------------
// 3) Main write kernel: HBM-write bound (537 MB of output), at the roofline.
//    PDL: stage pattern tile first, grid-dependency-sync, then coefficients.
// ---------------------------------------------------------------------------
__global__ void __launch_bounds__(256) main_kernel(const float* __restrict__ pattern,
                                                   float* __restrict__ out) {
    int b = blockIdx.y;
    int s0 = blockIdx.x * SCHUNK;
    int tid = threadIdx.x;
    int d = tid * 4;

    __shared__ float sp[(SCHUNK + 2) * 2];   // pattern[b, s0-2 .. s0+SCHUNK-1]
    if (tid < (SCHUNK + 2) * 2) {
        int s = s0 - 2 + (tid >> 1);
        int c = tid & 1;
        sp[tid] = (s >= 0) ? pattern[((size_t)b * S_ + s) * 2 + c] : 0.0f;
    }
#if __CUDA_ARCH__ >= 900
    cudaGridDependencySynchronize();
#endif
    float4 k1x = *(const float4*)(g_a1x + d);
    float4 k1y = *(const float4*)(g_a1y + d);
    float4 k2x = *(const float4*)(g_a2x + d);
    float4 k2y = *(const float4*)(g_a2y + d);
    float4 k3x = *(const float4*)(g_a3x + d);
    float4 k3y = *(const float4*)(g_a3y + d);
    float4 gg  = *(const float4*)(g_g + b * D_ + d);
    __syncthreads();

    float* op = out + ((size_t)b * S_ + s0) * D_ + d;

#pragma unroll
    for (int i = 0; i < SCHUNK; i++) {
        int s = s0 + i;
        float px = sp[(i + 2) * 2 + 0], py = sp[(i + 2) * 2 + 1];
        float mx = sp[(i + 1) * 2 + 0], my = sp[(i + 1) * 2 + 1];
        float nx = sp[(i + 0) * 2 + 0], ny = sp[(i + 0) * 2 + 1];

        float vx, vy, ax_, ay_;
        if (s == 0) {
            vx = 0.f; vy = 0.f; ax_ = 0.f; ay_ = 0.f;
        } else if (s == 1) {
            vx = px - mx; vy = py - my; ax_ = vx; ay_ = vy;
        } else {
            vx = px - mx; vy = py - my;
            ax_ = px - 2.f * mx + nx; ay_ = py - 2.f * my + ny;
        }

        float4 o;
        o.x = gg.x + k1x.x * px + k1y.x * py + k2x.x * vx + k2y.x * vy + k3x.x * ax_ + k3y.x * ay_;
        o.y = gg.y + k1x.y * px + k1y.y * py + k2x.y * vx + k2y.y * vy + k3x.y * ax_ + k3y.y * ay_;
        o.z = gg.z + k1x.z * px + k1y.z * py + k2x.z * vx + k2y.z * vy + k3x.z * ax_ + k3y.z * ay_;
        o.w = gg.w + k1x.w * px + k1y.w * py + k2x.w * vx + k2y.w * vy + k3x.w * ax_ + k3y.w * ay_;

        *(float4*)(op + (size_t)i * D_) = o;
    }
}

// ---------------------------------------------------------------------------
extern "C" void kernel_launch(void* const* d_in, const int* in_sizes, int n_in,
                              void* d_out, int out_size) {
    const float* pattern = (const float*)d_in[0];
    const float* Wp  = (const float*)d_in[1];
    const float* bp  = (const float*)d_in[2];
    const float* Wv  = (const float*)d_in[3];
    const float* bv  = (const float*)d_in[4];
    const float* Wa  = (const float*)d_in[5];
    const float* ba  = (const float*)d_in[6];
    const float* Wf  = (const float*)d_in[7];
    const float* bfr = (const float*)d_in[8];
    const float* Wo  = (const float*)d_in[9];
    const float* bo  = (const float*)d_in[10];
    float* out = (float*)d_out;

    pre_kernel<<<NDFT + NCOEFF, 1024>>>(pattern, Wp, bp, Wv, bv, Wa, ba,
                                        Wf, bfr, Wo, bo);
    gtab_kernel<<<dim3(B_, 4), 256>>>();

    // PDL on the final (dominant) kernel: overlap its launch/prologue with
    // gtab; main_kernel pre-syncs before touching precomputed tables.
    cudaLaunchAttribute at[1];
    at[0].id = cudaLaunchAttributeProgrammaticStreamSerialization;
    at[0].val.programmaticStreamSerializationAllowed = 1;

    cudaLaunchConfig_t cfg = {};
    cfg.gridDim = dim3(S_ / SCHUNK, B_);
    cfg.blockDim = dim3(256);
    cfg.stream = 0;
    cfg.attrs = at;
    cfg.numAttrs = 1;
    if (cudaLaunchKernelEx(&cfg, main_kernel, pattern, out) != cudaSuccess) {
        main_kernel<<<dim3(S_ / SCHUNK, B_), 256>>>(pattern, out);
    }
}

// round 14
// speedup vs baseline: 1.3832x; 1.0743x over previous
#include <cuda_runtime.h>
#include <math.h>

// ---------------------------------------------------------------------------
// PhysicsEmbedding: algebraic collapse of the whole pipeline.
//   B=32, S=4096, D=1024, H=256
// out[b,s,:] = A1·p[b,s] + A2·vel[b,s] + A3·acc[b,s] + g[b,:]
// g[b,:] = A4 @ freq[b] + c,  freq = |16-bin DFT| per channel
// ---------------------------------------------------------------------------

#define B_ 32
#define S_ 4096
#define D_ 1024
#define H_ 256
#define SCHUNK 16
#define NDFT 64                     // b*2 + chunk  (2 S-chunks of 2048)
#define NCOEFF 64                   // 16 d-rows per block
#define NPART 4                     // DFT partials per bin: chunk*2 + half

__device__ float2 g_dpart[B_ * 32 * NPART];    // DFT partials [b][j][q]
__device__ float g_a1x[D_], g_a1y[D_];
__device__ float g_a2x[D_], g_a2y[D_];
__device__ float g_a3x[D_], g_a3y[D_];
__device__ float g_A4T[32 * D_];               // transposed: [j][d]
__device__ float g_cbias[D_];
__device__ float g_g[B_ * D_];                 // per-batch constant vector

// ---------------------------------------------------------------------------
// 1) Fused precompute, one wave (128 blocks), prefetch double-buffered:
//    blocks [0,64):  DFT partials (float2 loads, next batch in flight).
//    blocks [64,128): coeff fold — 2 warps per d-row split the h range,
//                     8-wide prefetch keeps DRAM lines continuously in flight.
// ---------------------------------------------------------------------------
__global__ void __launch_bounds__(1024) pre_kernel(
        const float* __restrict__ pattern,
        const float* __restrict__ Wp, const float* __restrict__ bp,
        const float* __restrict__ Wv, const float* __restrict__ bv,
        const float* __restrict__ Wa, const float* __restrict__ ba,
        const float* __restrict__ Wf, const float* __restrict__ bfr,
        const float* __restrict__ Wo, const float* __restrict__ bo) {
    int bx = blockIdx.x;
    int tid = threadIdx.x;
    int lane = tid & 31;
    int w = tid >> 5;

    if (bx < NDFT) {
        // ---- DFT: warp w handles bin k=w&15, half=w>>4, BOTH channels ----
        int b = bx >> 1;
        int chunk = bx & 1;
        int k = w & 15;
        int half = w >> 4;
        int tl0 = half * 1024 + lane;          // local t within 2048-chunk
        int tg0 = chunk * 2048 + tl0;          // global t
        float a0 = (float)((k * tg0) & (S_ - 1)) * (-1.0f / 2048.0f);
        float as = (float)((k * 32) & (S_ - 1)) * (-1.0f / 2048.0f);
        float wr, wi, sr, si;
        sincospif(a0, &wi, &wr);
        sincospif(as, &si, &sr);

        const float2* pp2 = (const float2*)pattern + (size_t)b * S_ + chunk * 2048;
        float re0 = 0.f, im0 = 0.f, re1 = 0.f, im1 = 0.f;
        float2 xb[8], xn[8];
#pragma unroll
        for (int u = 0; u < 8; u++) xb[u] = pp2[tl0 + u * 32];
#pragma unroll
        for (int batch = 0; batch < 4; batch++) {
            if (batch < 3) {
#pragma unroll
                for (int u = 0; u < 8; u++)        // prefetch next batch
                    xn[u] = pp2[tl0 + ((batch + 1) * 8 + u) * 32];
            }
#pragma unroll
            for (int u = 0; u < 8; u++) {
                re0 += xb[u].x * wr;  im0 += xb[u].x * wi;
                re1 += xb[u].y * wr;  im1 += xb[u].y * wi;
                float nr = wr * sr - wi * si;      // w *= step
                float ni = wr * si + wi * sr;
                wr = nr; wi = ni;
            }
#pragma unroll
            for (int u = 0; u < 8; u++) xb[u] = xn[u];
        }
#pragma unroll
        for (int off = 16; off > 0; off >>= 1) {
            re0 += __shfl_down_sync(0xffffffffu, re0, off);
            im0 += __shfl_down_sync(0xffffffffu, im0, off);
            re1 += __shfl_down_sync(0xffffffffu, re1, off);
            im1 += __shfl_down_sync(0xffffffffu, im1, off);
        }
        if (lane == 0) {
            int q = chunk * 2 + half;
            g_dpart[(b * 32 + k) * NPART + q]      = make_float2(re0, im0); // ch0
            g_dpart[(b * 32 + 16 + k) * NPART + q] = make_float2(re1, im1); // ch1
        }
    } else {
        // ---- Coeff: 16 d-rows/block, 2 warps per row (h split), prefetch ----
        __shared__ float sA[16][32];
        int sub = tid >> 6;                        // d-row 0..15
        int d = (bx - NDFT) * 16 + sub;
        int isB = (tid >> 5) & 1;                  // warp A / warp B of this row
        const float* wo = Wo + (size_t)d * D_;

        // A4 half: h in [h0, h0+128), 16 batches of 8, prefetch double-buffer
        int h0 = isB ? 128 : 0;
        float ac0 = 0.f, ac1 = 0.f, ac2 = 0.f, ac3 = 0.f;
        float xb[8], xn[8];
#pragma unroll
        for (int u = 0; u < 8; u++) xb[u] = Wf[(h0 + u) * 32 + lane];
#pragma unroll 4
        for (int bb = 0; bb < 16; bb++) {
            if (bb < 15) {
#pragma unroll
                for (int u = 0; u < 8; u++)        // prefetch next batch
                    xn[u] = Wf[(h0 + (bb + 1) * 8 + u) * 32 + lane];
            }
            const float* wos = wo + 768 + h0 + bb * 8;
            float4 w0 = *(const float4*)(wos);
            float4 w1 = *(const float4*)(wos + 4);
            ac0 += xb[0] * w0.x + xb[4] * w1.x;
            ac1 += xb[1] * w0.y + xb[5] * w1.y;
            ac2 += xb[2] * w0.z + xb[6] * w1.z;
            ac3 += xb[3] * w0.w + xb[7] * w1.w;
#pragma unroll
            for (int u = 0; u < 8; u++) xb[u] = xn[u];
        }
        float a4 = (ac0 + ac1) + (ac2 + ac3);
        if (!isB) sA[sub][lane] = a4;
        __syncthreads();
        if (isB) g_A4T[lane * D_ + d] = a4 + sA[sub][lane];

        // Small coefficients + fused bias: warp A only (warp B overlaps above)
        if (!isB) {
            float a1x = 0, a1y = 0, a2x = 0, a2y = 0, a3x = 0, a3y = 0, bias = 0;
#pragma unroll
            for (int h = lane; h < H_; h += 32) {
                float w0 = wo[h];
                float w1 = wo[256 + h];
                float w2 = wo[512 + h];
                float w3 = wo[768 + h];
                a1x += w0 * Wp[h * 2 + 0];  a1y += w0 * Wp[h * 2 + 1];
                a2x += w1 * Wv[h * 2 + 0];  a2y += w1 * Wv[h * 2 + 1];
                a3x += w2 * Wa[h * 2 + 0];  a3y += w2 * Wa[h * 2 + 1];
                bias += w0 * bp[h] + w1 * bv[h] + w2 * ba[h] + w3 * bfr[h];
            }
#pragma unroll
            for (int off = 16; off > 0; off >>= 1) {
                a1x += __shfl_down_sync(0xffffffffu, a1x, off);
                a1y += __shfl_down_sync(0xffffffffu, a1y, off);
                a2x += __shfl_down_sync(0xffffffffu, a2x, off);
                a2y += __shfl_down_sync(0xffffffffu, a2y, off);
                a3x += __shfl_down_sync(0xffffffffu, a3x, off);
                a3y += __shfl_down_sync(0xffffffffu, a3y, off);
                bias += __shfl_down_sync(0xffffffffu, bias, off);
            }
            if (lane == 0) {
                g_a1x[d] = a1x; g_a1y[d] = a1y;
                g_a2x[d] = a2x; g_a2y[d] = a2y;
                g_a3x[d] = a3x; g_a3y[d] = a3y;
                g_cbias[d] = bias + bo[d];
            }
        }
    }
}

// ---------------------------------------------------------------------------
// 2) g[b,d] = cbias[d] + sum_j freq[b,j] * A4T[j][d].
//    grid (B_, 4) x 256 thr; thread = d within 256-chunk (coalesced A4T).
// ---------------------------------------------------------------------------
__global__ void __launch_bounds__(256) gtab_kernel() {
    int b = blockIdx.x;
    int d0 = blockIdx.y * 256;
    int tid = threadIdx.x;
    __shared__ float fr[32];
    if (tid < 32) {
        float re = 0.f, im = 0.f;
#pragma unroll
        for (int q = 0; q < NPART; q++) {
            float2 p = g_dpart[(b * 32 + tid) * NPART + q];
            re += p.x; im += p.y;
        }
        fr[tid] = sqrtf(re * re + im * im);
    }
    __syncthreads();

    int d = d0 + tid;
    float acc = g_cbias[d];
#pragma unroll
    for (int j = 0; j < 32; j++)
        acc += fr[j] * g_A4T[j * D_ + d];           // coalesced, fr broadcast
    g_g[b * D_ + d] = acc;
}

// ---------------------------------------------------------------------------
// 3) Main write kernel: HBM-write bound (537 MB of output), at the roofline.
//    PDL: stage pattern tile first, grid-dependency-sync, then coefficients.
// ---------------------------------------------------------------------------
__global__ void __launch_bounds__(256) main_kernel(const float* __restrict__ pattern,
                                                   float* __restrict__ out) {
    int b = blockIdx.y;
    int s0 = blockIdx.x * SCHUNK;
    int tid = threadIdx.x;
    int d = tid * 4;

    __shared__ float sp[(SCHUNK + 2) * 2];   // pattern[b, s0-2 .. s0+SCHUNK-1]
    if (tid < (SCHUNK + 2) * 2) {
        int s = s0 - 2 + (tid >> 1);
        int c = tid & 1;
        sp[tid] = (s >= 0) ? pattern[((size_t)b * S_ + s) * 2 + c] : 0.0f;
    }
#if __CUDA_ARCH__ >= 900
    cudaGridDependencySynchronize();
#endif
    float4 k1x = *(const float4*)(g_a1x + d);
    float4 k1y = *(const float4*)(g_a1y + d);
    float4 k2x = *(const float4*)(g_a2x + d);
    float4 k2y = *(const float4*)(g_a2y + d);
    float4 k3x = *(const float4*)(g_a3x + d);
    float4 k3y = *(const float4*)(g_a3y + d);
    float4 gg  = *(const float4*)(g_g + b * D_ + d);
    __syncthreads();

    float* op = out + ((size_t)b * S_ + s0) * D_ + d;

#pragma unroll
    for (int i = 0; i < SCHUNK; i++) {
        int s = s0 + i;
        float px = sp[(i + 2) * 2 + 0], py = sp[(i + 2) * 2 + 1];
        float mx = sp[(i + 1) * 2 + 0], my = sp[(i + 1) * 2 + 1];
        float nx = sp[(i + 0) * 2 + 0], ny = sp[(i + 0) * 2 + 1];

        float vx, vy, ax_, ay_;
        if (s == 0) {
            vx = 0.f; vy = 0.f; ax_ = 0.f; ay_ = 0.f;
        } else if (s == 1) {
            vx = px - mx; vy = py - my; ax_ = vx; ay_ = vy;
        } else {
            vx = px - mx; vy = py - my;
            ax_ = px - 2.f * mx + nx; ay_ = py - 2.f * my + ny;
        }

        float4 o;
        o.x = gg.x + k1x.x * px + k1y.x * py + k2x.x * vx + k2y.x * vy + k3x.x * ax_ + k3y.x * ay_;
        o.y = gg.y + k1x.y * px + k1y.y * py + k2x.y * vx + k2y.y * vy + k3x.y * ax_ + k3y.y * ay_;
        o.z = gg.z + k1x.z * px + k1y.z * py + k2x.z * vx + k2y.z * vy + k3x.z * ax_ + k3y.z * ay_;
        o.w = gg.w + k1x.w * px + k1y.w * py + k2x.w * vx + k2y.w * vy + k3x.w * ax_ + k3y.w * ay_;

        *(float4*)(op + (size_t)i * D_) = o;
    }
}

// ---------------------------------------------------------------------------
extern "C" void kernel_launch(void* const* d_in, const int* in_sizes, int n_in,
                              void* d_out, int out_size) {
    const float* pattern = (const float*)d_in[0];
    const float* Wp  = (const float*)d_in[1];
    const float* bp  = (const float*)d_in[2];
    const float* Wv  = (const float*)d_in[3];
    const float* bv  = (const float*)d_in[4];
    const float* Wa  = (const float*)d_in[5];
    const float* ba  = (const float*)d_in[6];
    const float* Wf  = (const float*)d_in[7];
    const float* bfr = (const float*)d_in[8];
    const float* Wo  = (const float*)d_in[9];
    const float* bo  = (const float*)d_in[10];
    float* out = (float*)d_out;

    pre_kernel<<<NDFT + NCOEFF, 1024>>>(pattern, Wp, bp, Wv, bv, Wa, ba,
                                        Wf, bfr, Wo, bo);
    gtab_kernel<<<dim3(B_, 4), 256>>>();

    // PDL on the final (dominant) kernel: overlap its launch/prologue with
    // gtab; main_kernel pre-syncs before touching precomputed tables.
    cudaLaunchAttribute at[1];
    at[0].id = cudaLaunchAttributeProgrammaticStreamSerialization;
    at[0].val.programmaticStreamSerializationAllowed = 1;

    cudaLaunchConfig_t cfg = {};
    cfg.gridDim = dim3(S_ / SCHUNK, B_);
    cfg.blockDim = dim3(256);
    cfg.stream = 0;
    cfg.attrs = at;
    cfg.numAttrs = 1;
    if (cudaLaunchKernelEx(&cfg, main_kernel, pattern, out) != cudaSuccess) {
        main_kernel<<<dim3(S_ / SCHUNK, B_), 256>>>(pattern, out);
    }
}

// round 15
// speedup vs baseline: 1.4116x; 1.0205x over previous
#include <cuda_runtime.h>
#include <math.h>

// ---------------------------------------------------------------------------
// PhysicsEmbedding: algebraic collapse of the whole pipeline.
//   B=32, S=4096, D=1024, H=256
// out[b,s,:] = A1·p[b,s] + A2·vel[b,s] + A3·acc[b,s] + g[b,:]
// g[b,:] = A4 @ freq[b] + c,  freq = |16-bin DFT| per channel
// ---------------------------------------------------------------------------

#define B_ 32
#define S_ 4096
#define D_ 1024
#define H_ 256
#define SCHUNK 16
#define NDFT 64                     // b*2 + chunk  (2 S-chunks of 2048)
#define NCOEFF 64                   // 16 d-rows per block
#define NPART 4                     // DFT partials per bin: chunk*2 + half

__device__ float2 g_dpart[B_ * 32 * NPART];    // DFT partials [b][j][q]
__device__ float g_a1x[D_], g_a1y[D_];
__device__ float g_a2x[D_], g_a2y[D_];
__device__ float g_a3x[D_], g_a3y[D_];
__device__ float g_A4T[32 * D_];               // transposed: [j][d]
__device__ float g_cbias[D_];
__device__ float g_g[B_ * D_];                 // per-batch constant vector

// ---------------------------------------------------------------------------
// 1) Fused precompute, one wave (128 blocks):
//    blocks [0,64):  DFT partials (float2 loads, prefetch double-buffer).
//    blocks [64,128): coeff fold — wo[768:1024] staged in smem (one burst),
//                     2 warps per d-row split h; ALL loops latency-hidden.
// ---------------------------------------------------------------------------
__global__ void __launch_bounds__(1024) pre_kernel(
        const float* __restrict__ pattern,
        const float* __restrict__ Wp, const float* __restrict__ bp,
        const float* __restrict__ Wv, const float* __restrict__ bv,
        const float* __restrict__ Wa, const float* __restrict__ ba,
        const float* __restrict__ Wf, const float* __restrict__ bfr,
        const float* __restrict__ Wo, const float* __restrict__ bo) {
    int bx = blockIdx.x;
    int tid = threadIdx.x;
    int lane = tid & 31;
    int w = tid >> 5;

    if (bx < NDFT) {
        // ---- DFT: warp w handles bin k=w&15, half=w>>4, BOTH channels ----
        int b = bx >> 1;
        int chunk = bx & 1;
        int k = w & 15;
        int half = w >> 4;
        int tl0 = half * 1024 + lane;          // local t within 2048-chunk
        int tg0 = chunk * 2048 + tl0;          // global t
        float a0 = (float)((k * tg0) & (S_ - 1)) * (-1.0f / 2048.0f);
        float as = (float)((k * 32) & (S_ - 1)) * (-1.0f / 2048.0f);
        float wr, wi, sr, si;
        sincospif(a0, &wi, &wr);
        sincospif(as, &si, &sr);

        const float2* pp2 = (const float2*)pattern + (size_t)b * S_ + chunk * 2048;
        float re0 = 0.f, im0 = 0.f, re1 = 0.f, im1 = 0.f;
        float2 xb[8], xn[8];
#pragma unroll
        for (int u = 0; u < 8; u++) xb[u] = pp2[tl0 + u * 32];
#pragma unroll
        for (int batch = 0; batch < 4; batch++) {
            if (batch < 3) {
#pragma unroll
                for (int u = 0; u < 8; u++)        // prefetch next batch
                    xn[u] = pp2[tl0 + ((batch + 1) * 8 + u) * 32];
            }
#pragma unroll
            for (int u = 0; u < 8; u++) {
                re0 += xb[u].x * wr;  im0 += xb[u].x * wi;
                re1 += xb[u].y * wr;  im1 += xb[u].y * wi;
                float nr = wr * sr - wi * si;      // w *= step
                float ni = wr * si + wi * sr;
                wr = nr; wi = ni;
            }
#pragma unroll
            for (int u = 0; u < 8; u++) xb[u] = xn[u];
        }
#pragma unroll
        for (int off = 16; off > 0; off >>= 1) {
            re0 += __shfl_down_sync(0xffffffffu, re0, off);
            im0 += __shfl_down_sync(0xffffffffu, im0, off);
            re1 += __shfl_down_sync(0xffffffffu, re1, off);
            im1 += __shfl_down_sync(0xffffffffu, im1, off);
        }
        if (lane == 0) {
            int q = chunk * 2 + half;
            g_dpart[(b * 32 + k) * NPART + q]      = make_float2(re0, im0); // ch0
            g_dpart[(b * 32 + 16 + k) * NPART + q] = make_float2(re1, im1); // ch1
        }
    } else {
        // ---- Coeff: 16 d-rows/block, 2 warps per row (h split) ----
        __shared__ float sWo[16][256];             // Wo[d0+r][768+c]
        __shared__ float sA[16][32];               // A4 partial from warp A
        __shared__ float sSm[16][2][8];            // small-coeff partials

        int cb = bx - NDFT;
        int d0 = cb * 16;
        int sub = tid >> 6;                        // d-row 0..15
        int d = d0 + sub;
        int isB = (tid >> 5) & 1;                  // warp A / warp B of this row
        int h0 = isB ? 128 : 0;
        const float* wo = Wo + (size_t)d * D_;

        // Stage wo[768:1024] for all 16 rows: 4096 floats, 4/thread, 1 burst
#pragma unroll
        for (int kk = 0; kk < 4; kk++) {
            int idx = tid + kk * 1024;
            int r = idx >> 8;
            int cc = idx & 255;
            sWo[r][cc] = Wo[(size_t)(d0 + r) * D_ + 768 + cc];
        }

        float bod = (lane == 0 && !isB) ? bo[d] : 0.f;   // prefetch bias

        // Wf first batch prefetch (concurrent with the smem stage)
        float xb[8], xn[8];
#pragma unroll
        for (int u = 0; u < 8; u++) xb[u] = Wf[(h0 + u) * 32 + lane];
        __syncthreads();

        // ---- A4 half: 16 batches, Wf prefetched, w3 from smem ----
        float ac0 = 0.f, ac1 = 0.f, ac2 = 0.f, ac3 = 0.f;
#pragma unroll 4
        for (int bb = 0; bb < 16; bb++) {
            if (bb < 15) {
#pragma unroll
                for (int u = 0; u < 8; u++)
                    xn[u] = Wf[(h0 + (bb + 1) * 8 + u) * 32 + lane];
            }
            const float* ws = &sWo[sub][h0 + bb * 8];      // LDS broadcast
            ac0 += ws[0] * xb[0] + ws[4] * xb[4];
            ac1 += ws[1] * xb[1] + ws[5] * xb[5];
            ac2 += ws[2] * xb[2] + ws[6] * xb[6];
            ac3 += ws[3] * xb[3] + ws[7] * xb[7];
#pragma unroll
            for (int u = 0; u < 8; u++) xb[u] = xn[u];
        }
        float a4 = (ac0 + ac1) + (ac2 + ac3);
        if (!isB) sA[sub][lane] = a4;

        // ---- Small coefficients, h-split across warps, double-buffered ----
        float a1x = 0, a1y = 0, a2x = 0, a2y = 0, a3x = 0, a3y = 0, bias = 0;
        int hh = h0 + lane;
        float w0b = wo[hh], w1b = wo[256 + hh], w2b = wo[512 + hh];
        float2 pb = ((const float2*)Wp)[hh];
        float2 vb = ((const float2*)Wv)[hh];
        float2 ab = ((const float2*)Wa)[hh];
        float bpb = bp[hh], bvb = bv[hh], bab = ba[hh], bfb = bfr[hh];
#pragma unroll
        for (int i = 0; i < 4; i++) {
            float w0n = 0.f, w1n = 0.f, w2n = 0.f;
            float2 pn = {0.f, 0.f}, vn = {0.f, 0.f}, an = {0.f, 0.f};
            float bpn = 0.f, bvn = 0.f, ban = 0.f, bfn = 0.f;
            if (i < 3) {
                int h = h0 + (i + 1) * 32 + lane;
                w0n = wo[h]; w1n = wo[256 + h]; w2n = wo[512 + h];
                pn = ((const float2*)Wp)[h];
                vn = ((const float2*)Wv)[h];
                an = ((const float2*)Wa)[h];
                bpn = bp[h]; bvn = bv[h]; ban = ba[h]; bfn = bfr[h];
            }
            float w3 = sWo[sub][h0 + i * 32 + lane];
            a1x += w0b * pb.x;  a1y += w0b * pb.y;
            a2x += w1b * vb.x;  a2y += w1b * vb.y;
            a3x += w2b * ab.x;  a3y += w2b * ab.y;
            bias += w0b * bpb + w1b * bvb + w2b * bab + w3 * bfb;
            w0b = w0n; w1b = w1n; w2b = w2n;
            pb = pn; vb = vn; ab = an;
            bpb = bpn; bvb = bvn; bab = ban; bfb = bfn;
        }
#pragma unroll
        for (int off = 16; off > 0; off >>= 1) {
            a1x += __shfl_down_sync(0xffffffffu, a1x, off);
            a1y += __shfl_down_sync(0xffffffffu, a1y, off);
            a2x += __shfl_down_sync(0xffffffffu, a2x, off);
            a2y += __shfl_down_sync(0xffffffffu, a2y, off);
            a3x += __shfl_down_sync(0xffffffffu, a3x, off);
            a3y += __shfl_down_sync(0xffffffffu, a3y, off);
            bias += __shfl_down_sync(0xffffffffu, bias, off);
        }
        if (lane == 0) {
            float* sm = sSm[sub][isB];
            sm[0] = a1x; sm[1] = a1y; sm[2] = a2x; sm[3] = a2y;
            sm[4] = a3x; sm[5] = a3y; sm[6] = bias;
        }
        __syncthreads();

        if (isB) g_A4T[lane * D_ + d] = a4 + sA[sub][lane];  // combine halves
        if (!isB && lane == 0) {
            const float* s0 = sSm[sub][0];
            const float* s1 = sSm[sub][1];
            g_a1x[d] = s0[0] + s1[0];  g_a1y[d] = s0[1] + s1[1];
            g_a2x[d] = s0[2] + s1[2];  g_a2y[d] = s0[3] + s1[3];
            g_a3x[d] = s0[4] + s1[4];  g_a3y[d] = s0[5] + s1[5];
            g_cbias[d] = s0[6] + s1[6] + bod;
        }
    }
}

// ---------------------------------------------------------------------------
// 2) g[b,d] = cbias[d] + sum_j freq[b,j] * A4T[j][d].
//    grid (B_, 4) x 256 thr; thread = d within 256-chunk (coalesced A4T).
// ---------------------------------------------------------------------------
__global__ void __launch_bounds__(256) gtab_kernel() {
    int b = blockIdx.x;
    int d0 = blockIdx.y * 256;
    int tid = threadIdx.x;
    __shared__ float fr[32];
    if (tid < 32) {
        float re = 0.f, im = 0.f;
#pragma unroll
        for (int q = 0; q < NPART; q++) {
            float2 p = g_dpart[(b * 32 + tid) * NPART + q];
            re += p.x; im += p.y;
        }
        fr[tid] = sqrtf(re * re + im * im);
    }
    __syncthreads();

    int d = d0 + tid;
    float acc = g_cbias[d];
#pragma unroll
    for (int j = 0; j < 32; j++)
        acc += fr[j] * g_A4T[j * D_ + d];           // coalesced, fr broadcast
    g_g[b * D_ + d] = acc;
}

// ---------------------------------------------------------------------------
// 3) Main write kernel: HBM-write bound (537 MB of output), at the roofline.
//    PDL: stage pattern tile first, grid-dependency-sync, then coefficients.
// ---------------------------------------------------------------------------
__global__ void __launch_bounds__(256) main_kernel(const float* __restrict__ pattern,
                                                   float* __restrict__ out) {
    int b = blockIdx.y;
    int s0 = blockIdx.x * SCHUNK;
    int tid = threadIdx.x;
    int d = tid * 4;

    __shared__ float sp[(SCHUNK + 2) * 2];   // pattern[b, s0-2 .. s0+SCHUNK-1]
    if (tid < (SCHUNK + 2) * 2) {
        int s = s0 - 2 + (tid >> 1);
        int c = tid & 1;
        sp[tid] = (s >= 0) ? pattern[((size_t)b * S_ + s) * 2 + c] : 0.0f;
    }
#if __CUDA_ARCH__ >= 900
    cudaGridDependencySynchronize();
#endif
    float4 k1x = *(const float4*)(g_a1x + d);
    float4 k1y = *(const float4*)(g_a1y + d);
    float4 k2x = *(const float4*)(g_a2x + d);
    float4 k2y = *(const float4*)(g_a2y + d);
    float4 k3x = *(const float4*)(g_a3x + d);
    float4 k3y = *(const float4*)(g_a3y + d);
    float4 gg  = *(const float4*)(g_g + b * D_ + d);
    __syncthreads();

    float* op = out + ((size_t)b * S_ + s0) * D_ + d;

#pragma unroll
    for (int i = 0; i < SCHUNK; i++) {
        int s = s0 + i;
        float px = sp[(i + 2) * 2 + 0], py = sp[(i + 2) * 2 + 1];
        float mx = sp[(i + 1) * 2 + 0], my = sp[(i + 1) * 2 + 1];
        float nx = sp[(i + 0) * 2 + 0], ny = sp[(i + 0) * 2 + 1];

        float vx, vy, ax_, ay_;
        if (s == 0) {
            vx = 0.f; vy = 0.f; ax_ = 0.f; ay_ = 0.f;
        } else if (s == 1) {
            vx = px - mx; vy = py - my; ax_ = vx; ay_ = vy;
        } else {
            vx = px - mx; vy = py - my;
            ax_ = px - 2.f * mx + nx; ay_ = py - 2.f * my + ny;
        }

        float4 o;
        o.x = gg.x + k1x.x * px + k1y.x * py + k2x.x * vx + k2y.x * vy + k3x.x * ax_ + k3y.x * ay_;
        o.y = gg.y + k1x.y * px + k1y.y * py + k2x.y * vx + k2y.y * vy + k3x.y * ax_ + k3y.y * ay_;
        o.z = gg.z + k1x.z * px + k1y.z * py + k2x.z * vx + k2y.z * vy + k3x.z * ax_ + k3y.z * ay_;
        o.w = gg.w + k1x.w * px + k1y.w * py + k2x.w * vx + k2y.w * vy + k3x.w * ax_ + k3y.w * ay_;

        *(float4*)(op + (size_t)i * D_) = o;
    }
}

// ---------------------------------------------------------------------------
extern "C" void kernel_launch(void* const* d_in, const int* in_sizes, int n_in,
                              void* d_out, int out_size) {
    const float* pattern = (const float*)d_in[0];
    const float* Wp  = (const float*)d_in[1];
    const float* bp  = (const float*)d_in[2];
    const float* Wv  = (const float*)d_in[3];
    const float* bv  = (const float*)d_in[4];
    const float* Wa  = (const float*)d_in[5];
    const float* ba  = (const float*)d_in[6];
    const float* Wf  = (const float*)d_in[7];
    const float* bfr = (const float*)d_in[8];
    const float* Wo  = (const float*)d_in[9];
    const float* bo  = (const float*)d_in[10];
    float* out = (float*)d_out;

    pre_kernel<<<NDFT + NCOEFF, 1024>>>(pattern, Wp, bp, Wv, bv, Wa, ba,
                                        Wf, bfr, Wo, bo);
    gtab_kernel<<<dim3(B_, 4), 256>>>();

    // PDL on the final (dominant) kernel: overlap its launch/prologue with
    // gtab; main_kernel pre-syncs before touching precomputed tables.
    cudaLaunchAttribute at[1];
    at[0].id = cudaLaunchAttributeProgrammaticStreamSerialization;
    at[0].val.programmaticStreamSerializationAllowed = 1;

    cudaLaunchConfig_t cfg = {};
    cfg.gridDim = dim3(S_ / SCHUNK, B_);
    cfg.blockDim = dim3(256);
    cfg.stream = 0;
    cfg.attrs = at;
    cfg.numAttrs = 1;
    if (cudaLaunchKernelEx(&cfg, main_kernel, pattern, out) != cudaSuccess) {
        main_kernel<<<dim3(S_ / SCHUNK, B_), 256>>>(pattern, out);
    }
}

// round 16
// speedup vs baseline: 1.4449x; 1.0236x over previous
#include <cuda_runtime.h>
#include <math.h>

// ---------------------------------------------------------------------------
// PhysicsEmbedding: algebraic collapse of the whole pipeline.
//   B=32, S=4096, D=1024, H=256
// out[b,s,:] = A1·p[b,s] + A2·vel[b,s] + A3·acc[b,s] + g[b,:]
// g[b,:] = A4 @ freq[b] + c,  freq = |16-bin DFT| per channel
// ---------------------------------------------------------------------------

#define B_ 32
#define S_ 4096
#define D_ 1024
#define H_ 256
#define SCHUNK 16
#define NDFT 64                     // b*2 + chunk  (2 S-chunks of 2048)
#define NCOEFF 64                   // 16 d-rows per block
#define NPART 4                     // DFT partials per bin: chunk*2 + half

__device__ float2 g_dpart[B_ * 32 * NPART];    // DFT partials [b][j][q]
__device__ float g_a1x[D_], g_a1y[D_];
__device__ float g_a2x[D_], g_a2y[D_];
__device__ float g_a3x[D_], g_a3y[D_];
__device__ float g_A4T[32 * D_];               // transposed: [j][d]
__device__ float g_cbias[D_];
__device__ float g_g[B_ * D_];                 // per-batch constant vector

// ---------------------------------------------------------------------------
// 1) Fused precompute, one wave (128 blocks):
//    blocks [0,64):  DFT partials (float2 loads, prefetch double-buffer).
//    blocks [64,128): coeff fold — ALL operands staged to smem in one burst
//                     (Wf, wo[768:1024], Wp/Wv/Wa, biases) + 12 upfront wo
//                     register prefetches; compute loops are fully resident.
// ---------------------------------------------------------------------------
__global__ void __launch_bounds__(1024) pre_kernel(
        const float* __restrict__ pattern,
        const float* __restrict__ Wp, const float* __restrict__ bp,
        const float* __restrict__ Wv, const float* __restrict__ bv,
        const float* __restrict__ Wa, const float* __restrict__ ba,
        const float* __restrict__ Wf, const float* __restrict__ bfr,
        const float* __restrict__ Wo, const float* __restrict__ bo) {
    __shared__ float  sWf[H_][32];             // 32KB: Wf[h][j]
    __shared__ float  sWo3[16][256];           // 16KB: Wo[d0+r][768+c]
    __shared__ float2 sWp2[H_], sWv2[H_], sWa2[H_];   // 6KB
    __shared__ float  sbB[4][H_];              // 4KB: bp,bv,ba,bf
    __shared__ float  sA[16][32];              // A4 partial from warp A
    __shared__ float  sSm[16][2][8];           // small-coeff partials

    int bx = blockIdx.x;
    int tid = threadIdx.x;
    int lane = tid & 31;
    int w = tid >> 5;

    if (bx < NDFT) {
        // ---- DFT: warp w handles bin k=w&15, half=w>>4, BOTH channels ----
        int b = bx >> 1;
        int chunk = bx & 1;
        int k = w & 15;
        int half = w >> 4;
        int tl0 = half * 1024 + lane;          // local t within 2048-chunk
        int tg0 = chunk * 2048 + tl0;          // global t
        float a0 = (float)((k * tg0) & (S_ - 1)) * (-1.0f / 2048.0f);
        float as = (float)((k * 32) & (S_ - 1)) * (-1.0f / 2048.0f);
        float wr, wi, sr, si;
        sincospif(a0, &wi, &wr);
        sincospif(as, &si, &sr);

        const float2* pp2 = (const float2*)pattern + (size_t)b * S_ + chunk * 2048;
        float re0 = 0.f, im0 = 0.f, re1 = 0.f, im1 = 0.f;
        float2 xb[8], xn[8];
#pragma unroll
        for (int u = 0; u < 8; u++) xb[u] = pp2[tl0 + u * 32];
#pragma unroll
        for (int batch = 0; batch < 4; batch++) {
            if (batch < 3) {
#pragma unroll
                for (int u = 0; u < 8; u++)        // prefetch next batch
                    xn[u] = pp2[tl0 + ((batch + 1) * 8 + u) * 32];
            }
#pragma unroll
            for (int u = 0; u < 8; u++) {
                re0 += xb[u].x * wr;  im0 += xb[u].x * wi;
                re1 += xb[u].y * wr;  im1 += xb[u].y * wi;
                float nr = wr * sr - wi * si;      // w *= step
                float ni = wr * si + wi * sr;
                wr = nr; wi = ni;
            }
#pragma unroll
            for (int u = 0; u < 8; u++) xb[u] = xn[u];
        }
#pragma unroll
        for (int off = 16; off > 0; off >>= 1) {
            re0 += __shfl_down_sync(0xffffffffu, re0, off);
            im0 += __shfl_down_sync(0xffffffffu, im0, off);
            re1 += __shfl_down_sync(0xffffffffu, re1, off);
            im1 += __shfl_down_sync(0xffffffffu, im1, off);
        }
        if (lane == 0) {
            int q = chunk * 2 + half;
            g_dpart[(b * 32 + k) * NPART + q]      = make_float2(re0, im0); // ch0
            g_dpart[(b * 32 + 16 + k) * NPART + q] = make_float2(re1, im1); // ch1
        }
    } else {
        // ---- Coeff: 16 d-rows/block, 2 warps per row (h split) ----
        int cb = bx - NDFT;
        int d0 = cb * 16;
        int sub = tid >> 6;                        // d-row 0..15
        int d = d0 + sub;
        int isB = (tid >> 5) & 1;                  // warp A / warp B of this row
        int h0 = isB ? 128 : 0;
        const float* wo = Wo + (size_t)d * D_;

        // ===== ONE block-wide burst: every operand into smem/regs =====
        // Wf: 8192 floats, 8 per thread (coalesced: consecutive tid = consecutive addr)
#pragma unroll
        for (int kk = 0; kk < 8; kk++) {
            int idx = tid + kk * 1024;
            ((float*)sWf)[idx] = Wf[idx];
        }
        // wo[768:1024] for all 16 rows: 4096 floats
#pragma unroll
        for (int kk = 0; kk < 4; kk++) {
            int idx = tid + kk * 1024;
            int r = idx >> 8;
            int cc = idx & 255;
            sWo3[r][cc] = Wo[(size_t)(d0 + r) * D_ + 768 + cc];
        }
        // small matrices + biases
        if (tid < 256) {
            sWp2[tid] = ((const float2*)Wp)[tid];
            sbB[0][tid] = bp[tid];
        } else if (tid < 512) {
            int i = tid - 256;
            sWv2[i] = ((const float2*)Wv)[i];
            sbB[1][i] = bv[i];
        } else if (tid < 768) {
            int i = tid - 512;
            sWa2[i] = ((const float2*)Wa)[i];
            sbB[2][i] = ba[i];
        } else {
            int i = tid - 768;
            sbB[3][i] = bfr[i];
        }
        // upfront register prefetch: this warp's wo[0:768] slice (12 LDGs)
        float w0r[4], w1r[4], w2r[4];
#pragma unroll
        for (int i = 0; i < 4; i++) {
            int h = h0 + i * 32 + lane;
            w0r[i] = wo[h];
            w1r[i] = wo[256 + h];
            w2r[i] = wo[512 + h];
        }
        float bod = (lane == 0 && !isB) ? bo[d] : 0.f;
        __syncthreads();

        // ===== A4 half: pure smem (LDS broadcast + conflict-free LDS) =====
        float ac0 = 0.f, ac1 = 0.f, ac2 = 0.f, ac3 = 0.f;
#pragma unroll
        for (int bb = 0; bb < 16; bb++) {
            int hb = h0 + bb * 8;
            const float* ws = &sWo3[sub][hb];
            ac0 += ws[0] * sWf[hb + 0][lane] + ws[4] * sWf[hb + 4][lane];
            ac1 += ws[1] * sWf[hb + 1][lane] + ws[5] * sWf[hb + 5][lane];
            ac2 += ws[2] * sWf[hb + 2][lane] + ws[6] * sWf[hb + 6][lane];
            ac3 += ws[3] * sWf[hb + 3][lane] + ws[7] * sWf[hb + 7][lane];
        }
        float a4 = (ac0 + ac1) + (ac2 + ac3);
        if (!isB) sA[sub][lane] = a4;

        // ===== Small coefficients: all operands already in regs/smem =====
        float a1x = 0, a1y = 0, a2x = 0, a2y = 0, a3x = 0, a3y = 0, bias = 0;
#pragma unroll
        for (int i = 0; i < 4; i++) {
            int h = h0 + i * 32 + lane;
            float w0 = w0r[i], w1 = w1r[i], w2 = w2r[i];
            float w3 = sWo3[sub][h];
            float2 pv = sWp2[h];
            float2 vv = sWv2[h];
            float2 av = sWa2[h];
            a1x += w0 * pv.x;  a1y += w0 * pv.y;
            a2x += w1 * vv.x;  a2y += w1 * vv.y;
            a3x += w2 * av.x;  a3y += w2 * av.y;
            bias += w0 * sbB[0][h] + w1 * sbB[1][h] + w2 * sbB[2][h] + w3 * sbB[3][h];
        }
#pragma unroll
        for (int off = 16; off > 0; off >>= 1) {
            a1x += __shfl_down_sync(0xffffffffu, a1x, off);
            a1y += __shfl_down_sync(0xffffffffu, a1y, off);
            a2x += __shfl_down_sync(0xffffffffu, a2x, off);
            a2y += __shfl_down_sync(0xffffffffu, a2y, off);
            a3x += __shfl_down_sync(0xffffffffu, a3x, off);
            a3y += __shfl_down_sync(0xffffffffu, a3y, off);
            bias += __shfl_down_sync(0xffffffffu, bias, off);
        }
        if (lane == 0) {
            float* sm = sSm[sub][isB];
            sm[0] = a1x; sm[1] = a1y; sm[2] = a2x; sm[3] = a2y;
            sm[4] = a3x; sm[5] = a3y; sm[6] = bias;
        }
        __syncthreads();

        if (isB) g_A4T[lane * D_ + d] = a4 + sA[sub][lane];  // combine halves
        if (!isB && lane == 0) {
            const float* s0 = sSm[sub][0];
            const float* s1 = sSm[sub][1];
            g_a1x[d] = s0[0] + s1[0];  g_a1y[d] = s0[1] + s1[1];
            g_a2x[d] = s0[2] + s1[2];  g_a2y[d] = s0[3] + s1[3];
            g_a3x[d] = s0[4] + s1[4];  g_a3y[d] = s0[5] + s1[5];
            g_cbias[d] = s0[6] + s1[6] + bod;
        }
    }
}

// ---------------------------------------------------------------------------
// 2) g[b,d] = cbias[d] + sum_j freq[b,j] * A4T[j][d].
//    grid (B_, 4) x 256 thr; thread = d within 256-chunk (coalesced A4T).
// ---------------------------------------------------------------------------
__global__ void __launch_bounds__(256) gtab_kernel() {
    int b = blockIdx.x;
    int d0 = blockIdx.y * 256;
    int tid = threadIdx.x;
    __shared__ float fr[32];
    if (tid < 32) {
        float re = 0.f, im = 0.f;
#pragma unroll
        for (int q = 0; q < NPART; q++) {
            float2 p = g_dpart[(b * 32 + tid) * NPART + q];
            re += p.x; im += p.y;
        }
        fr[tid] = sqrtf(re * re + im * im);
    }
    __syncthreads();

    int d = d0 + tid;
    float acc = g_cbias[d];
#pragma unroll
    for (int j = 0; j < 32; j++)
        acc += fr[j] * g_A4T[j * D_ + d];           // coalesced, fr broadcast
    g_g[b * D_ + d] = acc;
}

// ---------------------------------------------------------------------------
// 3) Main write kernel: HBM-write bound (537 MB of output), at the roofline.
//    PDL: stage pattern tile first, grid-dependency-sync, then coefficients.
// ---------------------------------------------------------------------------
__global__ void __launch_bounds__(256) main_kernel(const float* __restrict__ pattern,
                                                   float* __restrict__ out) {
    int b = blockIdx.y;
    int s0 = blockIdx.x * SCHUNK;
    int tid = threadIdx.x;
    int d = tid * 4;

    __shared__ float sp[(SCHUNK + 2) * 2];   // pattern[b, s0-2 .. s0+SCHUNK-1]
    if (tid < (SCHUNK + 2) * 2) {
        int s = s0 - 2 + (tid >> 1);
        int c = tid & 1;
        sp[tid] = (s >= 0) ? pattern[((size_t)b * S_ + s) * 2 + c] : 0.0f;
    }
#if __CUDA_ARCH__ >= 900
    cudaGridDependencySynchronize();
#endif
    float4 k1x = *(const float4*)(g_a1x + d);
    float4 k1y = *(const float4*)(g_a1y + d);
    float4 k2x = *(const float4*)(g_a2x + d);
    float4 k2y = *(const float4*)(g_a2y + d);
    float4 k3x = *(const float4*)(g_a3x + d);
    float4 k3y = *(const float4*)(g_a3y + d);
    float4 gg  = *(const float4*)(g_g + b * D_ + d);
    __syncthreads();

    float* op = out + ((size_t)b * S_ + s0) * D_ + d;

#pragma unroll
    for (int i = 0; i < SCHUNK; i++) {
        int s = s0 + i;
        float px = sp[(i + 2) * 2 + 0], py = sp[(i + 2) * 2 + 1];
        float mx = sp[(i + 1) * 2 + 0], my = sp[(i + 1) * 2 + 1];
        float nx = sp[(i + 0) * 2 + 0], ny = sp[(i + 0) * 2 + 1];

        float vx, vy, ax_, ay_;
        if (s == 0) {
            vx = 0.f; vy = 0.f; ax_ = 0.f; ay_ = 0.f;
        } else if (s == 1) {
            vx = px - mx; vy = py - my; ax_ = vx; ay_ = vy;
        } else {
            vx = px - mx; vy = py - my;
            ax_ = px - 2.f * mx + nx; ay_ = py - 2.f * my + ny;
        }

        float4 o;
        o.x = gg.x + k1x.x * px + k1y.x * py + k2x.x * vx + k2y.x * vy + k3x.x * ax_ + k3y.x * ay_;
        o.y = gg.y + k1x.y * px + k1y.y * py + k2x.y * vx + k2y.y * vy + k3x.y * ax_ + k3y.y * ay_;
        o.z = gg.z + k1x.z * px + k1y.z * py + k2x.z * vx + k2y.z * vy + k3x.z * ax_ + k3y.z * ay_;
        o.w = gg.w + k1x.w * px + k1y.w * py + k2x.w * vx + k2y.w * vy + k3x.w * ax_ + k3y.w * ay_;

        *(float4*)(op + (size_t)i * D_) = o;
    }
}

// ---------------------------------------------------------------------------
extern "C" void kernel_launch(void* const* d_in, const int* in_sizes, int n_in,
                              void* d_out, int out_size) {
    const float* pattern = (const float*)d_in[0];
    const float* Wp  = (const float*)d_in[1];
    const float* bp  = (const float*)d_in[2];
    const float* Wv  = (const float*)d_in[3];
    const float* bv  = (const float*)d_in[4];
    const float* Wa  = (const float*)d_in[5];
    const float* ba  = (const float*)d_in[6];
    const float* Wf  = (const float*)d_in[7];
    const float* bfr = (const float*)d_in[8];
    const float* Wo  = (const float*)d_in[9];
    const float* bo  = (const float*)d_in[10];
    float* out = (float*)d_out;

    pre_kernel<<<NDFT + NCOEFF, 1024>>>(pattern, Wp, bp, Wv, bv, Wa, ba,
                                        Wf, bfr, Wo, bo);
    gtab_kernel<<<dim3(B_, 4), 256>>>();

    // PDL on the final (dominant) kernel: overlap its launch/prologue with
    // gtab; main_kernel pre-syncs before touching precomputed tables.
    cudaLaunchAttribute at[1];
    at[0].id = cudaLaunchAttributeProgrammaticStreamSerialization;
    at[0].val.programmaticStreamSerializationAllowed = 1;

    cudaLaunchConfig_t cfg = {};
    cfg.gridDim = dim3(S_ / SCHUNK, B_);
    cfg.blockDim = dim3(256);
    cfg.stream = 0;
    cfg.attrs = at;
    cfg.numAttrs = 1;
    if (cudaLaunchKernelEx(&cfg, main_kernel, pattern, out) != cudaSuccess) {
        main_kernel<<<dim3(S_ / SCHUNK, B_), 256>>>(pattern, out);
    }
}

// round 17
// speedup vs baseline: 1.4765x; 1.0219x over previous
#include <cuda_runtime.h>
#include <math.h>

// ---------------------------------------------------------------------------
// PhysicsEmbedding: algebraic collapse of the whole pipeline.
//   B=32, S=4096, D=1024, H=256
// out[b,s,:] = A1·p[b,s] + A2·vel[b,s] + A3·acc[b,s] + g[b,:]
// g[b,:] = A4 @ freq[b] + c,  freq = |16-bin DFT| per channel
// ---------------------------------------------------------------------------

#define B_ 32
#define S_ 4096
#define D_ 1024
#define H_ 256
#define SCHUNK 16
#define NDFT 128                    // b*4 + chunk  (4 S-chunks of 1024)
#define NCOEFF 128                  // 8 d-rows per block
#define NPART 8                     // DFT partials per bin: chunk*2 + half
#define WFPAD 260                   // sWfT row stride (16B aligned, conflict-free)

__device__ float2 g_dpart[B_ * 32 * NPART];    // DFT partials [b][j][q]
__device__ float g_a1x[D_], g_a1y[D_];
__device__ float g_a2x[D_], g_a2y[D_];
__device__ float g_a3x[D_], g_a3y[D_];
__device__ float g_A4T[32 * D_];               // transposed: [j][d]
__device__ float g_cbias[D_];
__device__ float g_g[B_ * D_];                 // per-batch constant vector

// ---------------------------------------------------------------------------
// 1) Fused precompute, 256 blocks (2 per SM):
//    blocks [0,128):   DFT partials (float2 prefetch, 2 batches/warp).
//    blocks [128,256): coeff fold — 8 d-rows, 4 warps/row (h quartered),
//                      all operands staged to smem in one burst; Wf kept
//                      TRANSPOSED so each batch is 2 LDS.128.
// ---------------------------------------------------------------------------
__global__ void __launch_bounds__(1024) pre_kernel(
        const float* __restrict__ pattern,
        const float* __restrict__ Wp, const float* __restrict__ bp,
        const float* __restrict__ Wv, const float* __restrict__ bv,
        const float* __restrict__ Wa, const float* __restrict__ ba,
        const float* __restrict__ Wf, const float* __restrict__ bfr,
        const float* __restrict__ Wo, const float* __restrict__ bo) {
    __shared__ float  sWfT[32][WFPAD];         // ~33KB: Wf transposed [j][h]
    __shared__ float  sWo3[8][256];            // 8KB: Wo[d0+r][768+c]
    __shared__ float2 sWp2[H_], sWv2[H_], sWa2[H_];   // 6KB
    __shared__ float  sbB[4][H_];              // 4KB: bp,bv,ba,bf
    __shared__ float  sA4[8][4][32];           // 4KB: A4 quarter-partials
    __shared__ float  sSm[8][2][8];            // small-coeff partials

    int bx = blockIdx.x;
    int tid = threadIdx.x;
    int lane = tid & 31;
    int w = tid >> 5;

    if (bx < NDFT) {
        // ---- DFT: block (b, chunk of 1024); warp w: k=w&15, half=w>>4 ----
        int b = bx >> 2;
        int chunk = bx & 3;
        int k = w & 15;
        int half = w >> 4;
        int tl0 = half * 512 + lane;           // local t within 1024-chunk
        int tg0 = chunk * 1024 + tl0;          // global t
        float a0 = (float)((k * tg0) & (S_ - 1)) * (-1.0f / 2048.0f);
        float as = (float)((k * 32) & (S_ - 1)) * (-1.0f / 2048.0f);
        float wr, wi, sr, si;
        sincospif(a0, &wi, &wr);
        sincospif(as, &si, &sr);

        const float2* pp2 = (const float2*)pattern + (size_t)b * S_ + chunk * 1024;
        float re0 = 0.f, im0 = 0.f, re1 = 0.f, im1 = 0.f;
        float2 xb[8], xn[8];
#pragma unroll
        for (int u = 0; u < 8; u++) xb[u] = pp2[tl0 + u * 32];
#pragma unroll
        for (int batch = 0; batch < 2; batch++) {
            if (batch < 1) {
#pragma unroll
                for (int u = 0; u < 8; u++)        // prefetch next batch
                    xn[u] = pp2[tl0 + (8 + u) * 32];
            }
#pragma unroll
            for (int u = 0; u < 8; u++) {
                re0 += xb[u].x * wr;  im0 += xb[u].x * wi;
                re1 += xb[u].y * wr;  im1 += xb[u].y * wi;
                float nr = wr * sr - wi * si;      // w *= step
                float ni = wr * si + wi * sr;
                wr = nr; wi = ni;
            }
#pragma unroll
            for (int u = 0; u < 8; u++) xb[u] = xn[u];
        }
#pragma unroll
        for (int off = 16; off > 0; off >>= 1) {
            re0 += __shfl_down_sync(0xffffffffu, re0, off);
            im0 += __shfl_down_sync(0xffffffffu, im0, off);
            re1 += __shfl_down_sync(0xffffffffu, re1, off);
            im1 += __shfl_down_sync(0xffffffffu, im1, off);
        }
        if (lane == 0) {
            int q = chunk * 2 + half;
            g_dpart[(b * 32 + k) * NPART + q]      = make_float2(re0, im0); // ch0
            g_dpart[(b * 32 + 16 + k) * NPART + q] = make_float2(re1, im1); // ch1
        }
    } else {
        // ---- Coeff: 8 d-rows/block, 4 warps per row (h quartered) ----
        int cb = bx - NDFT;
        int d0 = cb * 8;
        int sub = tid >> 7;                        // d-row 0..7
        int q = (tid >> 5) & 3;                    // warp within row 0..3
        int d = d0 + sub;
        const float* wo = Wo + (size_t)d * D_;

        // ===== ONE block-wide burst =====
        // Wf transposed: 8192 floats, 8/thread (gmem coalesced)
#pragma unroll
        for (int kk = 0; kk < 8; kk++) {
            int idx = tid + kk * 1024;
            sWfT[idx & 31][idx >> 5] = Wf[idx];
        }
        // wo[768:1024] for all 8 rows: 2048 floats, 2/thread
#pragma unroll
        for (int kk = 0; kk < 2; kk++) {
            int idx = tid + kk * 1024;
            sWo3[idx >> 8][idx & 255] = Wo[(size_t)(d0 + (idx >> 8)) * D_ + 768 + (idx & 255)];
        }
        // small matrices + biases
        if (tid < 256) {
            sWp2[tid] = ((const float2*)Wp)[tid];
            sbB[0][tid] = bp[tid];
        } else if (tid < 512) {
            int i = tid - 256;
            sWv2[i] = ((const float2*)Wv)[i];
            sbB[1][i] = bv[i];
        } else if (tid < 768) {
            int i = tid - 512;
            sWa2[i] = ((const float2*)Wa)[i];
            sbB[2][i] = ba[i];
        } else {
            int i = tid - 768;
            sbB[3][i] = bfr[i];
        }
        // upfront register prefetch for small-coeff warps (q<2)
        float w0r[4], w1r[4], w2r[4];
        if (q < 2) {
#pragma unroll
            for (int i = 0; i < 4; i++) {
                int h = q * 128 + i * 32 + lane;
                w0r[i] = wo[h];
                w1r[i] = wo[256 + h];
                w2r[i] = wo[512 + h];
            }
        }
        float bod = (lane == 0 && q == 0) ? bo[d] : 0.f;
        __syncthreads();

        // ===== A4 quarter: h in [q*64, q*64+64), 8 batches of 8 =====
        int h0q = q * 64;
        float ac0 = 0.f, ac1 = 0.f, ac2 = 0.f, ac3 = 0.f;
#pragma unroll
        for (int bb = 0; bb < 8; bb++) {
            int hb = h0q + bb * 8;
            float4 wa = *(const float4*)&sWo3[sub][hb];        // broadcast
            float4 wb = *(const float4*)&sWo3[sub][hb + 4];
            float4 fa = *(const float4*)&sWfT[lane][hb];       // LDS.128
            float4 fb = *(const float4*)&sWfT[lane][hb + 4];
            ac0 += wa.x * fa.x + wb.x * fb.x;
            ac1 += wa.y * fa.y + wb.y * fb.y;
            ac2 += wa.z * fa.z + wb.z * fb.z;
            ac3 += wa.w * fa.w + wb.w * fb.w;
        }
        sA4[sub][q][lane] = (ac0 + ac1) + (ac2 + ac3);

        // ===== Small coefficients: warps q=0,1 (h halves), resident =====
        if (q < 2) {
            float a1x = 0, a1y = 0, a2x = 0, a2y = 0, a3x = 0, a3y = 0, bias = 0;
#pragma unroll
            for (int i = 0; i < 4; i++) {
                int h = q * 128 + i * 32 + lane;
                float w0 = w0r[i], w1 = w1r[i], w2 = w2r[i];
                float w3 = sWo3[sub][h];
                float2 pv = sWp2[h];
                float2 vv = sWv2[h];
                float2 av = sWa2[h];
                a1x += w0 * pv.x;  a1y += w0 * pv.y;
                a2x += w1 * vv.x;  a2y += w1 * vv.y;
                a3x += w2 * av.x;  a3y += w2 * av.y;
                bias += w0 * sbB[0][h] + w1 * sbB[1][h] + w2 * sbB[2][h] + w3 * sbB[3][h];
            }
#pragma unroll
            for (int off = 16; off > 0; off >>= 1) {
                a1x += __shfl_down_sync(0xffffffffu, a1x, off);
                a1y += __shfl_down_sync(0xffffffffu, a1y, off);
                a2x += __shfl_down_sync(0xffffffffu, a2x, off);
                a2y += __shfl_down_sync(0xffffffffu, a2y, off);
                a3x += __shfl_down_sync(0xffffffffu, a3x, off);
                a3y += __shfl_down_sync(0xffffffffu, a3y, off);
                bias += __shfl_down_sync(0xffffffffu, bias, off);
            }
            if (lane == 0) {
                float* sm = sSm[sub][q];
                sm[0] = a1x; sm[1] = a1y; sm[2] = a2x; sm[3] = a2y;
                sm[4] = a3x; sm[5] = a3y; sm[6] = bias;
            }
        }
        __syncthreads();

        // ===== Final combines =====
        if (q == 3)
            g_A4T[lane * D_ + d] = (sA4[sub][0][lane] + sA4[sub][1][lane])
                                 + (sA4[sub][2][lane] + sA4[sub][3][lane]);
        if (q == 0 && lane == 0) {
            const float* s0 = sSm[sub][0];
            const float* s1 = sSm[sub][1];
            g_a1x[d] = s0[0] + s1[0];  g_a1y[d] = s0[1] + s1[1];
            g_a2x[d] = s0[2] + s1[2];  g_a2y[d] = s0[3] + s1[3];
            g_a3x[d] = s0[4] + s1[4];  g_a3y[d] = s0[5] + s1[5];
            g_cbias[d] = s0[6] + s1[6] + bod;
        }
    }
}

// ---------------------------------------------------------------------------
// 2) g[b,d] = cbias[d] + sum_j freq[b,j] * A4T[j][d].
//    grid (B_, 4) x 256 thr; thread = d within 256-chunk (coalesced A4T).
// ---------------------------------------------------------------------------
__global__ void __launch_bounds__(256) gtab_kernel() {
    int b = blockIdx.x;
    int d0 = blockIdx.y * 256;
    int tid = threadIdx.x;
    __shared__ float fr[32];
    if (tid < 32) {
        float re = 0.f, im = 0.f;
#pragma unroll
        for (int q = 0; q < NPART; q++) {
            float2 p = g_dpart[(b * 32 + tid) * NPART + q];
            re += p.x; im += p.y;
        }
        fr[tid] = sqrtf(re * re + im * im);
    }
    __syncthreads();

    int d = d0 + tid;
    float acc = g_cbias[d];
#pragma unroll
    for (int j = 0; j < 32; j++)
        acc += fr[j] * g_A4T[j * D_ + d];           // coalesced, fr broadcast
    g_g[b * D_ + d] = acc;
}

// ---------------------------------------------------------------------------
// 3) Main write kernel: HBM-write bound (537 MB of output), at the roofline.
//    PDL: stage pattern tile first, grid-dependency-sync, then coefficients.
// ---------------------------------------------------------------------------
__global__ void __launch_bounds__(256) main_kernel(const float* __restrict__ pattern,
                                                   float* __restrict__ out) {
    int b = blockIdx.y;
    int s0 = blockIdx.x * SCHUNK;
    int tid = threadIdx.x;
    int d = tid * 4;

    __shared__ float sp[(SCHUNK + 2) * 2];   // pattern[b, s0-2 .. s0+SCHUNK-1]
    if (tid < (SCHUNK + 2) * 2) {
        int s = s0 - 2 + (tid >> 1);
        int c = tid & 1;
        sp[tid] = (s >= 0) ? pattern[((size_t)b * S_ + s) * 2 + c] : 0.0f;
    }
#if __CUDA_ARCH__ >= 900
    cudaGridDependencySynchronize();
#endif
    float4 k1x = *(const float4*)(g_a1x + d);
    float4 k1y = *(const float4*)(g_a1y + d);
    float4 k2x = *(const float4*)(g_a2x + d);
    float4 k2y = *(const float4*)(g_a2y + d);
    float4 k3x = *(const float4*)(g_a3x + d);
    float4 k3y = *(const float4*)(g_a3y + d);
    float4 gg  = *(const float4*)(g_g + b * D_ + d);
    __syncthreads();

    float* op = out + ((size_t)b * S_ + s0) * D_ + d;

#pragma unroll
    for (int i = 0; i < SCHUNK; i++) {
        int s = s0 + i;
        float px = sp[(i + 2) * 2 + 0], py = sp[(i + 2) * 2 + 1];
        float mx = sp[(i + 1) * 2 + 0], my = sp[(i + 1) * 2 + 1];
        float nx = sp[(i + 0) * 2 + 0], ny = sp[(i + 0) * 2 + 1];

        float vx, vy, ax_, ay_;
        if (s == 0) {
            vx = 0.f; vy = 0.f; ax_ = 0.f; ay_ = 0.f;
        } else if (s == 1) {
            vx = px - mx; vy = py - my; ax_ = vx; ay_ = vy;
        } else {
            vx = px - mx; vy = py - my;
            ax_ = px - 2.f * mx + nx; ay_ = py - 2.f * my + ny;
        }

        float4 o;
        o.x = gg.x + k1x.x * px + k1y.x * py + k2x.x * vx + k2y.x * vy + k3x.x * ax_ + k3y.x * ay_;
        o.y = gg.y + k1x.y * px + k1y.y * py + k2x.y * vx + k2y.y * vy + k3x.y * ax_ + k3y.y * ay_;
        o.z = gg.z + k1x.z * px + k1y.z * py + k2x.z * vx + k2y.z * vy + k3x.z * ax_ + k3y.z * ay_;
        o.w = gg.w + k1x.w * px + k1y.w * py + k2x.w * vx + k2y.w * vy + k3x.w * ax_ + k3y.w * ay_;

        *(float4*)(op + (size_t)i * D_) = o;
    }
}

// ---------------------------------------------------------------------------
extern "C" void kernel_launch(void* const* d_in, const int* in_sizes, int n_in,
                              void* d_out, int out_size) {
    const float* pattern = (const float*)d_in[0];
    const float* Wp  = (const float*)d_in[1];
    const float* bp  = (const float*)d_in[2];
    const float* Wv  = (const float*)d_in[3];
    const float* bv  = (const float*)d_in[4];
    const float* Wa  = (const float*)d_in[5];
    const float* ba  = (const float*)d_in[6];
    const float* Wf  = (const float*)d_in[7];
    const float* bfr = (const float*)d_in[8];
    const float* Wo  = (const float*)d_in[9];
    const float* bo  = (const float*)d_in[10];
    float* out = (float*)d_out;

    pre_kernel<<<NDFT + NCOEFF, 1024>>>(pattern, Wp, bp, Wv, bv, Wa, ba,
                                        Wf, bfr, Wo, bo);
    gtab_kernel<<<dim3(B_, 4), 256>>>();

    // PDL on the final (dominant) kernel: overlap its launch/prologue with
    // gtab; main_kernel pre-syncs before touching precomputed tables.
    cudaLaunchAttribute at[1];
    at[0].id = cudaLaunchAttributeProgrammaticStreamSerialization;
    at[0].val.programmaticStreamSerializationAllowed = 1;

    cudaLaunchConfig_t cfg = {};
    cfg.gridDim = dim3(S_ / SCHUNK, B_);
    cfg.blockDim = dim3(256);
    cfg.stream = 0;
    cfg.attrs = at;
    cfg.numAttrs = 1;
    if (cudaLaunchKernelEx(&cfg, main_kernel, pattern, out) != cudaSuccess) {
        main_kernel<<<dim3(S_ / SCHUNK, B_), 256>>>(pattern, out);
    }
}